// round 1
// baseline (speedup 1.0000x reference)
#include <cuda_runtime.h>
#include <math.h>

#define Bb 32
#define Nn 197
#define Cc 768
#define Hh 12
#define Dd 64
#define NN (Nn*Nn)      // 38809
#define BH (Bb*Hh)      // 384
#define M1 (Bb*Nn)      // 6304
#define SCALE 0.125f

// ---------------- scratch (no allocations allowed) ----------------
__device__ float g_q[BH*Nn*Dd];      // [B,H,N,D]
__device__ float g_k[BH*Nn*Dd];
__device__ float g_v[BH*Nn*Dd];
__device__ float g_attnW[(size_t)BH*NN];   // conv_w-mixed probs
__device__ float g_oh[(size_t)M1*Cc];      // out heads, [B,N,C] pre-proj

// ---------------- warp reductions ----------------
__device__ __forceinline__ float warpMax(float v){
#pragma unroll
    for (int o=16;o>0;o>>=1) v = fmaxf(v, __shfl_xor_sync(0xffffffffu, v, o));
    return v;
}
__device__ __forceinline__ float warpSum(float v){
#pragma unroll
    for (int o=16;o>0;o>>=1) v += __shfl_xor_sync(0xffffffffu, v, o);
    return v;
}

// =====================================================================
// K1: QKV GEMM  x[6304,768] @ w_qkv[768,2304] -> scatter into g_q/g_k/g_v
// 64x64 tile, BK=16, 256 threads, 4x4 per thread
// =====================================================================
__global__ __launch_bounds__(256) void k_qkv(const float* __restrict__ X,
                                             const float* __restrict__ W)
{
    __shared__ float As[16][65];
    __shared__ float Bs[16][65];
    const int tid = threadIdx.x;
    const int tx = tid & 15, ty = tid >> 4;
    const int row0 = blockIdx.y * 64;
    const int col0 = blockIdx.x * 64;
    float acc[4][4] = {};

    for (int kt = 0; kt < 768; kt += 16) {
#pragma unroll
        for (int l = 0; l < 4; l++) {
            int e = tid + l*256;
            int ar = e >> 4, ac = e & 15;
            int gr = row0 + ar;
            As[ac][ar] = (gr < M1) ? X[gr*768 + kt + ac] : 0.f;
        }
#pragma unroll
        for (int l = 0; l < 4; l++) {
            int e = tid + l*256;
            int br = e >> 6, bc = e & 63;
            Bs[br][bc] = W[(kt+br)*2304 + col0 + bc];
        }
        __syncthreads();
#pragma unroll
        for (int kk = 0; kk < 16; kk++) {
            float a[4], bfr[4];
#pragma unroll
            for (int i=0;i<4;i++) a[i]   = As[kk][ty*4+i];
#pragma unroll
            for (int j=0;j<4;j++) bfr[j] = Bs[kk][tx*4+j];
#pragma unroll
            for (int i=0;i<4;i++)
#pragma unroll
                for (int j=0;j<4;j++)
                    acc[i][j] += a[i]*bfr[j];
        }
        __syncthreads();
    }
    // tile spans exactly one (t,h) block since col0 is 64-aligned
    const int colbase = col0;
    const int t = colbase / 768;
    const int rem = colbase - t*768;
    const int h = rem >> 6;
    float* dst = (t==0) ? g_q : (t==1) ? g_k : g_v;
#pragma unroll
    for (int i=0;i<4;i++) {
        int row = row0 + ty*4 + i;
        if (row >= M1) continue;
        int b = row / Nn, n = row - b*Nn;
        float* drow = dst + ((b*Hh + h)*Nn + n)*Dd;
#pragma unroll
        for (int j=0;j<4;j++) {
            int d = tx*4 + j;          // 0..63 within the head
            drow[d] = acc[i][j];
        }
    }
}

// =====================================================================
// K2: batched NT GEMM: out[z,n,m] = alpha * sum_d A[z,n,d]*B[z,m,d]
// mode 0: A=g_q, B=g_k ; mode 1: A=g_v, B=g_v
// =====================================================================
__global__ __launch_bounds__(256) void k_bgemm_nt(int mode,
                                                  float* __restrict__ out,
                                                  float alpha)
{
    __shared__ float As[16][65];
    __shared__ float Bs[16][65];
    const int z = blockIdx.z;
    const float* Az = (mode==0 ? g_q : g_v) + (size_t)z*Nn*Dd;
    const float* Bz = (mode==0 ? g_k : g_v) + (size_t)z*Nn*Dd;
    float* Oz = out + (size_t)z*NN;
    const int tid = threadIdx.x;
    const int tx = tid & 15, ty = tid >> 4;
    const int n0 = blockIdx.y * 64;
    const int m0 = blockIdx.x * 64;
    float acc[4][4] = {};

    for (int kt = 0; kt < 64; kt += 16) {
#pragma unroll
        for (int l = 0; l < 4; l++) {
            int e = tid + l*256;
            int r = e >> 4, c = e & 15;
            As[c][r] = (n0+r < Nn) ? Az[(n0+r)*Dd + kt + c] : 0.f;
            Bs[c][r] = (m0+r < Nn) ? Bz[(m0+r)*Dd + kt + c] : 0.f;
        }
        __syncthreads();
#pragma unroll
        for (int kk = 0; kk < 16; kk++) {
            float a[4], bfr[4];
#pragma unroll
            for (int i=0;i<4;i++) a[i]   = As[kk][ty*4+i];
#pragma unroll
            for (int j=0;j<4;j++) bfr[j] = Bs[kk][tx*4+j];
#pragma unroll
            for (int i=0;i<4;i++)
#pragma unroll
                for (int j=0;j<4;j++)
                    acc[i][j] += a[i]*bfr[j];
        }
        __syncthreads();
    }
#pragma unroll
    for (int i=0;i<4;i++) {
        int n = n0 + ty*4 + i;
        if (n >= Nn) continue;
#pragma unroll
        for (int j=0;j<4;j++) {
            int m = m0 + tx*4 + j;
            if (m >= Nn) continue;
            Oz[n*Nn + m] = alpha * acc[i][j];
        }
    }
}

// =====================================================================
// K3: in-place row softmax, one warp per row of length 197
// =====================================================================
__global__ __launch_bounds__(128) void k_softmax_rows(float* __restrict__ data,
                                                      int nrows)
{
    int warp = (blockIdx.x * blockDim.x + threadIdx.x) >> 5;
    int lane = threadIdx.x & 31;
    if (warp >= nrows) return;
    float* row = data + (size_t)warp * Nn;
    float v[7];
    float mx = -INFINITY;
#pragma unroll
    for (int i=0;i<7;i++) {
        int m = lane + i*32;
        v[i] = (m < Nn) ? row[m] : -INFINITY;
        mx = fmaxf(mx, v[i]);
    }
    mx = warpMax(mx);
    float s = 0.f;
#pragma unroll
    for (int i=0;i<7;i++) {
        int m = lane + i*32;
        v[i] = (m < Nn) ? __expf(v[i]-mx) : 0.f;
        s += v[i];
    }
    s = warpSum(s);
    float inv = 1.f / s;
#pragma unroll
    for (int i=0;i<7;i++) {
        int m = lane + i*32;
        if (m < Nn) row[m] = v[i]*inv;
    }
}

// =====================================================================
// K4: fused conv_l -> softmax -> (write probs) -> conv_w -> g_attnW
// one block per (b,n); smem holds all 12 heads of the row
// =====================================================================
__global__ __launch_bounds__(256) void k_convmix(const float* __restrict__ scores,
                                                 const float* __restrict__ wl,
                                                 const float* __restrict__ ww,
                                                 float* __restrict__ probs)
{
    __shared__ float s_in[12][200];
    __shared__ float s_p [12][200];
    __shared__ float s_wl[144];
    __shared__ float s_ww[144];
    __shared__ float red[8];

    const int bn = blockIdx.x;
    const int b = bn / Nn, n = bn - b*Nn;
    const int tid = threadIdx.x;
    const int lane = tid & 31, wid = tid >> 5;

    if (tid < 144) { s_wl[tid] = wl[tid]; s_ww[tid] = ww[tid]; }
    for (int e = tid; e < 12*Nn; e += 256) {
        int h = e / Nn, m = e - h*Nn;
        s_in[h][m] = scores[(size_t)(b*Hh + h)*NN + n*Nn + m];
    }
    __syncthreads();

    const int m = tid;
    for (int o = 0; o < 12; o++) {
        float x = 0.f, val = -INFINITY;
        if (m < Nn) {
#pragma unroll
            for (int h=0; h<12; h++) x += s_wl[o*12+h] * s_in[h][m];
            val = x;
        }
        float wv = warpMax(val);
        if (lane==0) red[wid] = wv;
        __syncthreads();
        if (tid==0) { float t=red[0]; for (int i=1;i<8;i++) t=fmaxf(t,red[i]); red[0]=t; }
        __syncthreads();
        float mx = red[0];
        float e  = (m < Nn) ? __expf(x - mx) : 0.f;
        __syncthreads();
        float ws = warpSum(e);
        if (lane==0) red[wid] = ws;
        __syncthreads();
        if (tid==0) { float t=0.f; for (int i=0;i<8;i++) t+=red[i]; red[0]=t; }
        __syncthreads();
        float inv = 1.f / red[0];
        if (m < Nn) {
            float p = e * inv;
            s_p[o][m] = p;
            probs[(size_t)(b*Hh + o)*NN + n*Nn + m] = p;
        }
        __syncthreads();
    }

    // conv_w on the probabilities, to scratch
    for (int e2 = tid; e2 < 12*Nn; e2 += 256) {
        int o = e2 / Nn, mm = e2 - o*Nn;
        float x = 0.f;
#pragma unroll
        for (int h=0; h<12; h++) x += s_ww[o*12+h] * s_p[h][mm];
        g_attnW[(size_t)(b*Hh + o)*NN + n*Nn + mm] = x;
    }
}

// =====================================================================
// K5: out = attnW @ v per (b,h), epilogue into [B,N,C] scratch
// =====================================================================
__global__ __launch_bounds__(256) void k_av()
{
    __shared__ float As[16][65];
    __shared__ float Bs[16][65];
    const int z = blockIdx.z;
    const int b = z / Hh, h = z - b*Hh;
    const float* Az = g_attnW + (size_t)z*NN;
    const float* Vz = g_v + (size_t)z*Nn*Dd;
    const int tid = threadIdx.x;
    const int tx = tid & 15, ty = tid >> 4;
    const int n0 = blockIdx.y * 64;
    float acc[4][4] = {};

    for (int kt = 0; kt < Nn; kt += 16) {
#pragma unroll
        for (int l = 0; l < 4; l++) {
            int e = tid + l*256;
            int r = e >> 4, c = e & 15;
            As[c][r] = (n0+r < Nn && kt+c < Nn) ? Az[(n0+r)*Nn + kt + c] : 0.f;
        }
#pragma unroll
        for (int l = 0; l < 4; l++) {
            int e = tid + l*256;
            int r = e >> 6, c = e & 63;
            Bs[r][c] = (kt+r < Nn) ? Vz[(kt+r)*Dd + c] : 0.f;
        }
        __syncthreads();
#pragma unroll
        for (int kk = 0; kk < 16; kk++) {
            float a[4], bfr[4];
#pragma unroll
            for (int i=0;i<4;i++) a[i]   = As[kk][ty*4+i];
#pragma unroll
            for (int j=0;j<4;j++) bfr[j] = Bs[kk][tx*4+j];
#pragma unroll
            for (int i=0;i<4;i++)
#pragma unroll
                for (int j=0;j<4;j++)
                    acc[i][j] += a[i]*bfr[j];
        }
        __syncthreads();
    }
#pragma unroll
    for (int i=0;i<4;i++) {
        int n = n0 + ty*4 + i;
        if (n >= Nn) continue;
        float* drow = g_oh + ((size_t)(b*Nn + n))*Cc + h*Dd;
#pragma unroll
        for (int j=0;j<4;j++) {
            int d = tx*4 + j;
            drow[d] = acc[i][j];
        }
    }
}

// =====================================================================
// K6: proj GEMM  g_oh[6304,768] @ w_proj[768,768] + bias -> out0
// =====================================================================
__global__ __launch_bounds__(256) void k_proj(const float* __restrict__ Wp,
                                              const float* __restrict__ bias,
                                              float* __restrict__ out0)
{
    __shared__ float As[16][65];
    __shared__ float Bs[16][65];
    const int tid = threadIdx.x;
    const int tx = tid & 15, ty = tid >> 4;
    const int row0 = blockIdx.y * 64;
    const int col0 = blockIdx.x * 64;
    float acc[4][4] = {};

    for (int kt = 0; kt < 768; kt += 16) {
#pragma unroll
        for (int l = 0; l < 4; l++) {
            int e = tid + l*256;
            int ar = e >> 4, ac = e & 15;
            int gr = row0 + ar;
            As[ac][ar] = (gr < M1) ? g_oh[(size_t)gr*768 + kt + ac] : 0.f;
        }
#pragma unroll
        for (int l = 0; l < 4; l++) {
            int e = tid + l*256;
            int br = e >> 6, bc = e & 63;
            Bs[br][bc] = Wp[(kt+br)*768 + col0 + bc];
        }
        __syncthreads();
#pragma unroll
        for (int kk = 0; kk < 16; kk++) {
            float a[4], bfr[4];
#pragma unroll
            for (int i=0;i<4;i++) a[i]   = As[kk][ty*4+i];
#pragma unroll
            for (int j=0;j<4;j++) bfr[j] = Bs[kk][tx*4+j];
#pragma unroll
            for (int i=0;i<4;i++)
#pragma unroll
                for (int j=0;j<4;j++)
                    acc[i][j] += a[i]*bfr[j];
        }
        __syncthreads();
    }
#pragma unroll
    for (int i=0;i<4;i++) {
        int row = row0 + ty*4 + i;
        if (row >= M1) continue;
#pragma unroll
        for (int j=0;j<4;j++) {
            int col = col0 + tx*4 + j;
            out0[(size_t)row*768 + col] = acc[i][j] + bias[col];
        }
    }
}

// =====================================================================
extern "C" void kernel_launch(void* const* d_in, const int* in_sizes, int n_in,
                              void* d_out, int out_size)
{
    const float* x       = (const float*)d_in[0];
    const float* w_qkv   = (const float*)d_in[1];
    const float* w_proj  = (const float*)d_in[2];
    const float* b_proj  = (const float*)d_in[3];
    const float* w_convl = (const float*)d_in[4];
    const float* w_convw = (const float*)d_in[5];

    float* out0       = (float*)d_out;                       // attention_output [B,N,C]
    float* out_scores = out0 + (size_t)M1*Cc;                // [B,H,N,N]
    float* out_probs  = out_scores + (size_t)BH*NN;          // [B,H,N,N]
    float* out_vm     = out_probs  + (size_t)BH*NN;          // [B,H,N,N]

    // 1) QKV projection
    k_qkv<<<dim3(36, 99), 256>>>(x, w_qkv);

    // 2) attention scores = (q*scale) k^T  and raw scaled v v^T
    k_bgemm_nt<<<dim3(4, 4, BH), 256>>>(0, out_scores, SCALE);
    k_bgemm_nt<<<dim3(4, 4, BH), 256>>>(1, out_vm, SCALE);

    // 3) softmax(v v^T * scale) -> value_map (in place)
    {
        int nrows = BH * Nn;            // 75648
        int blocks = (nrows + 3) / 4;   // 4 warps / block
        k_softmax_rows<<<blocks, 128>>>(out_vm, nrows);
    }

    // 4) conv_l -> softmax -> probs, conv_w -> g_attnW
    k_convmix<<<M1, 256>>>(out_scores, w_convl, w_convw, out_probs);

    // 5) attnW @ v -> head-interleaved scratch
    k_av<<<dim3(1, 4, BH), 256>>>();

    // 6) projection + bias -> attention_output
    k_proj<<<dim3(12, 99), 256>>>(w_proj, b_proj, out0);
}